// round 4
// baseline (speedup 1.0000x reference)
#include <cuda_runtime.h>
#include <cstdint>

#define BB 4
#define SS 1024
#define DD 768
#define HH 12
#define HDD 64

// tcgen05 is only legal in the sm_103a (arch-accelerated) compile pass.
// The harness also emits a plain compute_103 PTX pass; give it a SIMT body.
#if defined(__CUDA_ARCH_FEAT_SM103_ALL) || defined(__CUDA_ARCH_FEAT_SM100_ALL) || defined(__CUDA_ARCH_FEAT_SM101_ALL)
#define TC_OK 1
#else
#define TC_OK 0
#endif

// ---------------- device scratch (allocation-free: __device__ globals) -------
__device__ float g_qf[BB * SS * DD];
__device__ float g_kf[BB * SS * DD];
__device__ float g_vf[BB * SS * DD];
__device__ float g_ctx[BB * SS * DD];
__device__ float g_L0[BB * HH * SS * SS];
__device__ float g_A [BB * HH * SS * SS];

// ======================= small PTX helpers ==================================
__device__ __forceinline__ uint32_t smem_u32(const void* p) {
    uint32_t a;
    asm("{ .reg .u64 t; cvta.to.shared.u64 t, %1; cvt.u32.u64 %0, t; }"
        : "=r"(a) : "l"(p));
    return a;
}

#if TC_OK
__device__ __forceinline__ bool elect_one() {
    uint32_t p;
    asm volatile("{ .reg .pred p; elect.sync _|p, 0xFFFFFFFF; selp.b32 %0, 1, 0, p; }"
                 : "=r"(p));
    return p != 0;
}
__device__ __forceinline__ void mbar_init(uint32_t a, uint32_t cnt) {
    asm volatile("mbarrier.init.shared.b64 [%0], %1;" :: "r"(a), "r"(cnt) : "memory");
}
__device__ __forceinline__ void mbar_wait(uint32_t a, uint32_t parity) {
    asm volatile(
        "{\n\t.reg .pred P;\n\t"
        "LAB_%=:\n\t"
        "mbarrier.try_wait.parity.acquire.cta.shared::cta.b64 P, [%0], %1, 0x989680;\n\t"
        "@!P bra LAB_%=;\n\t}"
        :: "r"(a), "r"(parity) : "memory");
}
__device__ __forceinline__ uint64_t sdesc(uint32_t addr) {
    // SW128, Blackwell version=1, SBO=64, LBO=1 (K-major, 128B rows)
    return ((uint64_t)2 << 61) | ((uint64_t)1 << 46) | ((uint64_t)64 << 32)
         | ((uint64_t)1 << 16) | ((addr >> 4) & 0x3FFF);
}
// idesc: dtype=F32(1)@4, atype=TF32(2)@7, btype=TF32(2)@10, N=128->16@17, M=128->8@24
#define TC_IDESC 0x8200910u

__device__ __forceinline__ void mma_tf32_ss(uint32_t d, uint64_t a, uint64_t b,
                                            uint32_t en) {
    asm volatile(
        "{\n\t.reg .pred p;\n\t"
        "setp.ne.u32 p, %5, 0;\n\t"
        "tcgen05.mma.cta_group::1.kind::tf32 [%0], %1, %2, %3, {%4, %4, %4, %4}, p;\n\t}"
        :: "r"(d), "l"(a), "l"(b), "r"(TC_IDESC), "r"(0u), "r"(en) : "memory");
}
__device__ __forceinline__ void tc_commit(uint32_t mbar) {
    asm volatile(
        "tcgen05.commit.cta_group::1.mbarrier::arrive::one.shared::cluster.b64 [%0];"
        :: "r"(mbar) : "memory");
}
#endif // TC_OK

#define SWZ(off) ((off) ^ (((off) >> 3) & 0x70))

__device__ __forceinline__ float thi(float x) {
    return __uint_as_float(__float_as_uint(x) & 0xFFFFE000u);
}
__device__ __forceinline__ void split4(float4 v, float4& h, float4& l) {
    h.x = thi(v.x); h.y = thi(v.y); h.z = thi(v.z); h.w = thi(v.w);
    l.x = thi(v.x - h.x); l.y = thi(v.y - h.y);
    l.z = thi(v.z - h.z); l.w = thi(v.w - h.w);
}

// ============== tcgen05 tf32 (3x split) GEMM: Y = X @ W^T + bias =============
#define SM_BUF   65536      // per-buffer: A_hi|A_lo|B_hi|B_lo (4 x 16KB)
#define SM_MBAR  131072
#define SM_TPTR  131088
#define SM_BIAS  131104
#define SM_TOTAL 131648

#if TC_OK
__device__ __forceinline__ void tc_chunk(
    const float* __restrict__ X, const float* __restrict__ W, char* sm,
    uint32_t sbase, int bm, int bn, int c, int bf, int& ph, int t,
    uint32_t tmem_d, uint32_t mbar)
{
    const int k0 = c * 32;
    char* base = sm + bf * SM_BUF;
    if (t < 128) {
        if (c >= 2) { mbar_wait(mbar, ph); ph ^= 1; }
#pragma unroll
        for (int i = 0; i < 8; i++) {
            int idx = i * 128 + t;
            int row = idx >> 3, c4 = idx & 7;
            float4 a = *(const float4*)(X + (size_t)(bm + row) * 768 + k0 + c4 * 4);
            float4 b = *(const float4*)(W + (size_t)(bn + row) * 768 + k0 + c4 * 4);
            uint32_t off = SWZ((uint32_t)(row * 128 + c4 * 16));
            float4 h, l;
            split4(a, h, l);
            *(float4*)(base + off)         = h;
            *(float4*)(base + 16384 + off) = l;
            split4(b, h, l);
            *(float4*)(base + 32768 + off) = h;
            *(float4*)(base + 49152 + off) = l;
        }
        asm volatile("fence.proxy.async.shared::cta;" ::: "memory");
    }
    __syncthreads();
    if (t >= 128) {
        if (elect_one()) {
            uint64_t ah = sdesc(sbase + bf * SM_BUF);
            uint64_t al = ah + (16384 >> 4);
            uint64_t bh = ah + (32768 >> 4);
            uint64_t bl = ah + (49152 >> 4);
#pragma unroll
            for (int s = 0; s < 4; s++) {
                uint64_t off = s * 2;
                mma_tf32_ss(tmem_d, ah + off, bh + off, (c > 0) || (s > 0));
                mma_tf32_ss(tmem_d, al + off, bh + off, 1u);
                mma_tf32_ss(tmem_d, ah + off, bl + off, 1u);
            }
            tc_commit(mbar);
        }
    }
}
#endif

__global__ __launch_bounds__(160, 1) void k_gemm_tc(
    const float* __restrict__ X0, const float* __restrict__ X1,
    const float* __restrict__ X2, const float* __restrict__ W,
    const float* __restrict__ bias,
    float* __restrict__ Y0, float* __restrict__ Y1, float* __restrict__ Y2)
{
    extern __shared__ char sm[];
    const int z = blockIdx.z;
    const float* X = (z == 0) ? X0 : (z == 1) ? X1 : X2;
    float* Y = (z == 0) ? Y0 : (z == 1) ? Y1 : Y2;

    const int t = threadIdx.x;
    const int bm = blockIdx.y * 128, bn = blockIdx.x * 128;

#if TC_OK
    const uint32_t sbase = smem_u32(sm);
    const uint32_t mb0 = sbase + SM_MBAR, mb1 = sbase + SM_MBAR + 8;

    if (t >= 128) {
        if (t == 128) { mbar_init(mb0, 1); mbar_init(mb1, 1); }
        asm volatile(
            "tcgen05.alloc.cta_group::1.sync.aligned.shared::cta.b32 [%0], %1;"
            :: "r"(sbase + SM_TPTR), "r"(128u) : "memory");
    } else {
        ((float*)(sm + SM_BIAS))[t] = bias[bn + t];
    }
    __syncthreads();

    uint32_t tmem;
    asm volatile("ld.shared.b32 %0, [%1];" : "=r"(tmem) : "r"(sbase + SM_TPTR));

    int ph0 = 0, ph1 = 0;
    for (int cc = 0; cc < 24; cc += 2) {
        tc_chunk(X, W, sm, sbase, bm, bn, cc,     0, ph0, t, tmem, mb0);
        tc_chunk(X, W, sm, sbase, bm, bn, cc + 1, 1, ph1, t, tmem, mb1);
    }

    // drain + epilogue: ONLY the t<128 threads (their ph0/ph1 track the true
    // parity). Warp 4's ph was never toggled — it waiting here was the
    // round-3 deadlock (it waited for a 13th commit that never comes).
    if (t < 128) {
        mbar_wait(mb0, ph0);
        mbar_wait(mb1, ph1);
        asm volatile("tcgen05.fence::after_thread_sync;" ::: "memory");

        float* yrow = Y + (size_t)(bm + t) * 768 + bn;
        const float* sb = (const float*)(sm + SM_BIAS);
#pragma unroll
        for (int nb = 0; nb < 4; nb++) {
            uint32_t r[32];
            asm volatile(
                "tcgen05.ld.sync.aligned.32x32b.x32.b32 "
                "{%0, %1, %2, %3, %4, %5, %6, %7, "
                " %8, %9, %10, %11, %12, %13, %14, %15, "
                " %16, %17, %18, %19, %20, %21, %22, %23, "
                " %24, %25, %26, %27, %28, %29, %30, %31}, [%32];"
                : "=r"(r[0]), "=r"(r[1]), "=r"(r[2]), "=r"(r[3]),
                  "=r"(r[4]), "=r"(r[5]), "=r"(r[6]), "=r"(r[7]),
                  "=r"(r[8]), "=r"(r[9]), "=r"(r[10]), "=r"(r[11]),
                  "=r"(r[12]), "=r"(r[13]), "=r"(r[14]), "=r"(r[15]),
                  "=r"(r[16]), "=r"(r[17]), "=r"(r[18]), "=r"(r[19]),
                  "=r"(r[20]), "=r"(r[21]), "=r"(r[22]), "=r"(r[23]),
                  "=r"(r[24]), "=r"(r[25]), "=r"(r[26]), "=r"(r[27]),
                  "=r"(r[28]), "=r"(r[29]), "=r"(r[30]), "=r"(r[31])
                : "r"(tmem + nb * 32));
            asm volatile("tcgen05.wait::ld.sync.aligned;" ::: "memory");
            float f[32];
#pragma unroll
            for (int j = 0; j < 32; j++)
                f[j] = __uint_as_float(r[j]) + sb[nb * 32 + j];
#pragma unroll
            for (int j4 = 0; j4 < 8; j4++)
                *(float4*)(yrow + nb * 32 + j4 * 4) =
                    make_float4(f[j4 * 4], f[j4 * 4 + 1], f[j4 * 4 + 2], f[j4 * 4 + 3]);
        }
        asm volatile("tcgen05.fence::before_thread_sync;" ::: "memory");
    }
    __syncthreads();
    if (t >= 128) {
        asm volatile("tcgen05.relinquish_alloc_permit.cta_group::1.sync.aligned;");
        asm volatile("tcgen05.dealloc.cta_group::1.sync.aligned.b32 %0, %1;"
                     :: "r"(tmem), "r"(128u));
    }
#else
    // SIMT fallback for the non-'a' PTX pass. Never selected at runtime on
    // GB300 (exact sm_103a SASS is embedded), but kept correct.
    if (t < 128) {
        for (int n = 0; n < 128; n++) {
            float acc = bias[bn + n];
            const float* xr = X + (size_t)(bm + t) * 768;
            const float* wr = W + (size_t)(bn + n) * 768;
            for (int kk = 0; kk < 768; kk++) acc = fmaf(xr[kk], wr[kk], acc);
            Y[(size_t)(bm + t) * 768 + bn + n] = acc;
        }
    }
#endif
}

// ---------------- FFMA-only exp ---------------------------------------------
__device__ __forceinline__ float fexp(float x) {
    float t = fmaxf(x * 1.4426950408889634f, -126.0f);
    float fi = floorf(t);
    float f = t - fi;
    float p = 1.5403530e-4f;
    p = fmaf(p, f, 1.3333558e-3f);
    p = fmaf(p, f, 9.6181291e-3f);
    p = fmaf(p, f, 5.5504109e-2f);
    p = fmaf(p, f, 2.4022651e-1f);
    p = fmaf(p, f, 6.9314718e-1f);
    p = fmaf(p, f, 1.0f);
    int e = (int)fi;
    return p * __int_as_float((e + 127) << 23);
}

// ---------------- K2: raw logits  L0[b,h,q,k] = 0.125 * qh . kh -------------
__global__ __launch_bounds__(256) void k_qk()
{
    __shared__ float As[8][128];
    __shared__ float Bs[8][128];
    const int bh = blockIdx.z;
    const int b = bh / HH, h = bh % HH;
    const float* Aq = g_qf + b * SS * DD + h * HDD;
    const float* Bk = g_kf + b * SS * DD + h * HDD;
    float* C = g_L0 + (size_t)bh * SS * SS;

    const int t  = threadIdx.x;
    const int tx = t & 15, ty = t >> 4;
    const int bm = blockIdx.y * 128, bn = blockIdx.x * 128;
    const int arow = t >> 1, ac = (t & 1) * 4;

    float acc[8][8];
#pragma unroll
    for (int i = 0; i < 8; i++)
#pragma unroll
        for (int j = 0; j < 8; j++) acc[i][j] = 0.f;

    for (int k0 = 0; k0 < 64; k0 += 8) {
        float4 av = *(const float4*)(Aq + (bm + arow) * DD + k0 + ac);
        float4 bv = *(const float4*)(Bk + (bn + arow) * DD + k0 + ac);
        __syncthreads();
        As[ac + 0][arow] = av.x; As[ac + 1][arow] = av.y;
        As[ac + 2][arow] = av.z; As[ac + 3][arow] = av.w;
        Bs[ac + 0][arow] = bv.x; Bs[ac + 1][arow] = bv.y;
        Bs[ac + 2][arow] = bv.z; Bs[ac + 3][arow] = bv.w;
        __syncthreads();
#pragma unroll
        for (int kk = 0; kk < 8; kk++) {
            float a[8], bfr[8];
            *(float4*)(a)       = *(const float4*)&As[kk][ty * 8];
            *(float4*)(a + 4)   = *(const float4*)&As[kk][ty * 8 + 4];
            *(float4*)(bfr)     = *(const float4*)&Bs[kk][tx * 8];
            *(float4*)(bfr + 4) = *(const float4*)&Bs[kk][tx * 8 + 4];
#pragma unroll
            for (int i = 0; i < 8; i++)
#pragma unroll
                for (int j = 0; j < 8; j++)
                    acc[i][j] = fmaf(a[i], bfr[j], acc[i][j]);
        }
    }

#pragma unroll
    for (int i = 0; i < 8; i++) {
        float* cr = C + (size_t)(bm + ty * 8 + i) * SS + bn + tx * 8;
        *(float4*)(cr)     = make_float4(acc[i][0] * 0.125f, acc[i][1] * 0.125f,
                                         acc[i][2] * 0.125f, acc[i][3] * 0.125f);
        *(float4*)(cr + 4) = make_float4(acc[i][4] * 0.125f, acc[i][5] * 0.125f,
                                         acc[i][6] * 0.125f, acc[i][7] * 0.125f);
    }
}

// ---------------- K3: fused Wl-mix -> softmax -> Wp-mix ----------------------
__global__ __launch_bounds__(256) void k_softmix(
    const float* __restrict__ Wl, const float* __restrict__ bl,
    const float* __restrict__ Wp, const float* __restrict__ bp)
{
    __shared__ float sWl[144], sWp[144], sbl[12], sbp[12];
    __shared__ float red[12][8];
    __shared__ float sstat[12];
    __shared__ float sinv[12];

    const int t = threadIdx.x;
    if (t < 144) { sWl[t] = Wl[t]; sWp[t] = Wp[t]; }
    if (t < 12)  { sbl[t] = bl[t]; sbp[t] = bp[t]; }
    __syncthreads();

    const int q = blockIdx.x, b = blockIdx.y;
    const size_t base = (size_t)(b * HH) * SS * SS + (size_t)q * SS;

    float L[12][4];
#pragma unroll
    for (int g = 0; g < 12; g++) {
        float bv = sbl[g];
        L[g][0] = bv; L[g][1] = bv; L[g][2] = bv; L[g][3] = bv;
    }
#pragma unroll
    for (int h = 0; h < 12; h++) {
        float4 r = ((const float4*)(g_L0 + base + (size_t)h * SS * SS))[t];
#pragma unroll
        for (int g = 0; g < 12; g++) {
            float w = sWl[g * 12 + h];
            L[g][0] = fmaf(w, r.x, L[g][0]);
            L[g][1] = fmaf(w, r.y, L[g][1]);
            L[g][2] = fmaf(w, r.z, L[g][2]);
            L[g][3] = fmaf(w, r.w, L[g][3]);
        }
    }

    float mx[12];
#pragma unroll
    for (int g = 0; g < 12; g++)
        mx[g] = fmaxf(fmaxf(L[g][0], L[g][1]), fmaxf(L[g][2], L[g][3]));
#pragma unroll
    for (int o = 16; o; o >>= 1)
#pragma unroll
        for (int g = 0; g < 12; g++)
            mx[g] = fmaxf(mx[g], __shfl_xor_sync(0xffffffffu, mx[g], o));
    if ((t & 31) == 0)
#pragma unroll
        for (int g = 0; g < 12; g++) red[g][t >> 5] = mx[g];
    __syncthreads();
    if (t < 12) {
        float m = red[t][0];
#pragma unroll
        for (int w = 1; w < 8; w++) m = fmaxf(m, red[t][w]);
        sstat[t] = m;
    }
    __syncthreads();

    float smr[12];
#pragma unroll
    for (int g = 0; g < 12; g++) {
        float m = sstat[g];
        float p0 = fexp(L[g][0] - m);
        float p1 = fexp(L[g][1] - m);
        float p2 = fexp(L[g][2] - m);
        float p3 = fexp(L[g][3] - m);
        L[g][0] = p0; L[g][1] = p1; L[g][2] = p2; L[g][3] = p3;
        smr[g] = (p0 + p1) + (p2 + p3);
    }
#pragma unroll
    for (int o = 16; o; o >>= 1)
#pragma unroll
        for (int g = 0; g < 12; g++)
            smr[g] += __shfl_xor_sync(0xffffffffu, smr[g], o);
    __syncthreads();
    if ((t & 31) == 0)
#pragma unroll
        for (int g = 0; g < 12; g++) red[g][t >> 5] = smr[g];
    __syncthreads();
    if (t < 12) {
        float s = red[t][0];
#pragma unroll
        for (int w = 1; w < 8; w++) s += red[t][w];
        sinv[t] = 1.0f / s;
    }
    __syncthreads();

#pragma unroll
    for (int h = 0; h < 12; h++) {
        float iv = sinv[h];
        L[h][0] *= iv; L[h][1] *= iv; L[h][2] *= iv; L[h][3] *= iv;
    }

#pragma unroll
    for (int g = 0; g < 12; g++) {
        float bv = sbp[g];
        float a0 = bv, a1 = bv, a2 = bv, a3 = bv;
#pragma unroll
        for (int h = 0; h < 12; h++) {
            float w = sWp[g * 12 + h];
            a0 = fmaf(w, L[h][0], a0);
            a1 = fmaf(w, L[h][1], a1);
            a2 = fmaf(w, L[h][2], a2);
            a3 = fmaf(w, L[h][3], a3);
        }
        ((float4*)(g_A + base + (size_t)g * SS * SS))[t] = make_float4(a0, a1, a2, a3);
    }
}

// ---------------- K4: ctx = A @ V (per b,g) ----------------------------------
__global__ __launch_bounds__(256) void k_av()
{
    __shared__ float As[16][128];
    __shared__ float Bs[16][64];
    const int bh = blockIdx.y;
    const int b = bh / HH, g = bh % HH;
    const float* A = g_A + (size_t)bh * SS * SS;
    const float* V = g_vf + b * SS * DD + g * HDD;
    float* C = g_ctx + b * SS * DD + g * HDD;

    const int t  = threadIdx.x;
    const int tx = t & 15, ty = t >> 4;
    const int bm = blockIdx.x * 128;

    float acc[8][4];
#pragma unroll
    for (int i = 0; i < 8; i++)
#pragma unroll
        for (int j = 0; j < 4; j++) acc[i][j] = 0.f;

    for (int k0 = 0; k0 < SS; k0 += 16) {
        float4 av[2];
#pragma unroll
        for (int i = 0; i < 2; i++) {
            int c4 = ((t * 2 + i) & 3) << 2;
            av[i] = *(const float4*)(A + (size_t)(bm + (t >> 1)) * SS + k0 + c4);
        }
        float4 bv = *(const float4*)(V + (k0 + (t >> 4)) * DD + ((t & 15) << 2));
        __syncthreads();
#pragma unroll
        for (int i = 0; i < 2; i++) {
            int c4 = ((t * 2 + i) & 3) << 2;
            int r = t >> 1;
            As[c4 + 0][r] = av[i].x; As[c4 + 1][r] = av[i].y;
            As[c4 + 2][r] = av[i].z; As[c4 + 3][r] = av[i].w;
        }
        *(float4*)&Bs[t >> 4][(t & 15) << 2] = bv;
        __syncthreads();
#pragma unroll
        for (int kk = 0; kk < 16; kk++) {
            float a[8], b4[4];
            *(float4*)(a)     = *(const float4*)&As[kk][ty * 8];
            *(float4*)(a + 4) = *(const float4*)&As[kk][ty * 8 + 4];
            *(float4*)(b4)    = *(const float4*)&Bs[kk][tx * 4];
#pragma unroll
            for (int i = 0; i < 8; i++)
#pragma unroll
                for (int j = 0; j < 4; j++)
                    acc[i][j] = fmaf(a[i], b4[j], acc[i][j]);
        }
    }

#pragma unroll
    for (int i = 0; i < 8; i++) {
        *(float4*)(C + (size_t)(bm + ty * 8 + i) * DD + tx * 4) =
            make_float4(acc[i][0], acc[i][1], acc[i][2], acc[i][3]);
    }
}

// ---------------- launch ------------------------------------------------------
extern "C" void kernel_launch(void* const* d_in, const int* in_sizes, int n_in,
                              void* d_out, int out_size)
{
    const float* q  = (const float*)d_in[0];
    const float* k  = (const float*)d_in[1];
    const float* v  = (const float*)d_in[2];
    const float* Wq = (const float*)d_in[3];
    const float* bq = (const float*)d_in[4];
    const float* Wl = (const float*)d_in[5];
    const float* bl = (const float*)d_in[6];
    const float* Wp = (const float*)d_in[7];
    const float* bp = (const float*)d_in[8];
    const float* Wf = (const float*)d_in[9];
    const float* bf = (const float*)d_in[10];
    float* out = (float*)d_out;

    cudaFuncSetAttribute(k_gemm_tc,
                         cudaFuncAttributeMaxDynamicSharedMemorySize, SM_TOTAL);

    float* qf;  cudaGetSymbolAddress((void**)&qf,  g_qf);
    float* kf;  cudaGetSymbolAddress((void**)&kf,  g_kf);
    float* vf;  cudaGetSymbolAddress((void**)&vf,  g_vf);
    float* ctx; cudaGetSymbolAddress((void**)&ctx, g_ctx);

    k_gemm_tc<<<dim3(6, 32, 3), 160, SM_TOTAL>>>(q, k, v, Wq, bq, qf, kf, vf);
    k_qk     <<<dim3(8, 8, 48),  256>>>();
    k_softmix<<<dim3(1024, 4),   256>>>(Wl, bl, Wp, bp);
    k_av     <<<dim3(8, 48),     256>>>();
    k_gemm_tc<<<dim3(6, 32, 1), 160, SM_TOTAL>>>(ctx, ctx, ctx, Wf, bf, out, out, out);
}

// round 5
// speedup vs baseline: 1.8218x; 1.8218x over previous
#include <cuda_runtime.h>
#include <cstdint>

#define BB 4
#define SS 1024
#define DD 768
#define HH 12
#define HDD 64

#if defined(__CUDA_ARCH_FEAT_SM103_ALL) || defined(__CUDA_ARCH_FEAT_SM100_ALL) || defined(__CUDA_ARCH_FEAT_SM101_ALL)
#define TC_OK 1
#else
#define TC_OK 0
#endif

// ---------------- device scratch -------------------------------------------
__device__ float g_qf [BB * SS * DD];
__device__ float g_kf [BB * SS * DD];
__device__ float g_vf [BB * SS * DD];
__device__ float g_ctx[BB * SS * DD];
__device__ float g_L0[BB * HH * SS * SS];
__device__ float g_A [BB * HH * SS * SS];
__device__ float g_vth[BB * HH * HDD * SS];   // V^T hi, [bh][64][1024]
__device__ float g_vtl[BB * HH * HDD * SS];   // V^T lo

// ======================= helpers ============================================
__device__ __forceinline__ uint32_t smem_u32(const void* p) {
    uint32_t a;
    asm("{ .reg .u64 t; cvta.to.shared.u64 t, %1; cvt.u32.u64 %0, t; }"
        : "=r"(a) : "l"(p));
    return a;
}
#define SWZ(off) ((off) ^ (((off) >> 3) & 0x70))

__device__ __forceinline__ float thi(float x) {
    return __uint_as_float(__float_as_uint(x) & 0xFFFFE000u);
}
__device__ __forceinline__ void split4(float4 v, float4& h, float4& l) {
    h.x = thi(v.x); h.y = thi(v.y); h.z = thi(v.z); h.w = thi(v.w);
    l.x = v.x - h.x; l.y = v.y - h.y; l.z = v.z - h.z; l.w = v.w - h.w;
}

#if TC_OK
__device__ __forceinline__ bool elect_one() {
    uint32_t p;
    asm volatile("{ .reg .pred p; elect.sync _|p, 0xFFFFFFFF; selp.b32 %0, 1, 0, p; }"
                 : "=r"(p));
    return p != 0;
}
__device__ __forceinline__ void mbar_init(uint32_t a, uint32_t cnt) {
    asm volatile("mbarrier.init.shared.b64 [%0], %1;" :: "r"(a), "r"(cnt) : "memory");
}
__device__ __forceinline__ void mbar_wait(uint32_t a, uint32_t parity) {
    asm volatile(
        "{\n\t.reg .pred P;\n\t"
        "LAB_%=:\n\t"
        "mbarrier.try_wait.parity.acquire.cta.shared::cta.b64 P, [%0], %1, 0x989680;\n\t"
        "@!P bra LAB_%=;\n\t}"
        :: "r"(a), "r"(parity) : "memory");
}
__device__ __forceinline__ uint64_t sdesc(uint32_t addr) {
    return ((uint64_t)2 << 61) | ((uint64_t)1 << 46) | ((uint64_t)64 << 32)
         | ((uint64_t)1 << 16) | ((addr >> 4) & 0x3FFF);
}
// idesc: dtype=F32@4, a/b=TF32@7/@10, N/8@17, M/16@24
#define IDESC_N128 0x8200910u
#define IDESC_N64  0x8100910u

__device__ __forceinline__ void mma_tf32(uint32_t d, uint64_t a, uint64_t b,
                                         uint32_t idesc, uint32_t en) {
    asm volatile(
        "{\n\t.reg .pred p;\n\t"
        "setp.ne.u32 p, %5, 0;\n\t"
        "tcgen05.mma.cta_group::1.kind::tf32 [%0], %1, %2, %3, {%4, %4, %4, %4}, p;\n\t}"
        :: "r"(d), "l"(a), "l"(b), "r"(idesc), "r"(0u), "r"(en) : "memory");
}
__device__ __forceinline__ void tc_commit(uint32_t mbar) {
    asm volatile(
        "tcgen05.commit.cta_group::1.mbarrier::arrive::one.shared::cluster.b64 [%0];"
        :: "r"(mbar) : "memory");
}
// 12 MMAs for one K=32 chunk: 3-term hi/lo split x 4 K=8 substeps
__device__ __forceinline__ void issue12(uint32_t tmem, uint32_t buf,
        uint32_t alo, uint32_t bho, uint32_t blo, uint32_t idesc, bool first) {
    uint64_t ah = sdesc(buf), al = sdesc(buf + alo);
    uint64_t bh = sdesc(buf + bho), bl = sdesc(buf + blo);
#pragma unroll
    for (int s = 0; s < 4; s++) {
        uint64_t o = (uint64_t)(s * 2);
        mma_tf32(tmem, ah + o, bh + o, idesc, !(first && s == 0));
        mma_tf32(tmem, al + o, bh + o, idesc, 1u);
        mma_tf32(tmem, ah + o, bl + o, idesc, 1u);
    }
}
__device__ __forceinline__ void ldtm32(uint32_t* r, uint32_t addr) {
    asm volatile(
        "tcgen05.ld.sync.aligned.32x32b.x32.b32 "
        "{%0, %1, %2, %3, %4, %5, %6, %7, "
        " %8, %9, %10, %11, %12, %13, %14, %15, "
        " %16, %17, %18, %19, %20, %21, %22, %23, "
        " %24, %25, %26, %27, %28, %29, %30, %31}, [%32];"
        : "=r"(r[0]), "=r"(r[1]), "=r"(r[2]), "=r"(r[3]),
          "=r"(r[4]), "=r"(r[5]), "=r"(r[6]), "=r"(r[7]),
          "=r"(r[8]), "=r"(r[9]), "=r"(r[10]), "=r"(r[11]),
          "=r"(r[12]), "=r"(r[13]), "=r"(r[14]), "=r"(r[15]),
          "=r"(r[16]), "=r"(r[17]), "=r"(r[18]), "=r"(r[19]),
          "=r"(r[20]), "=r"(r[21]), "=r"(r[22]), "=r"(r[23]),
          "=r"(r[24]), "=r"(r[25]), "=r"(r[26]), "=r"(r[27]),
          "=r"(r[28]), "=r"(r[29]), "=r"(r[30]), "=r"(r[31])
        : "r"(addr));
    asm volatile("tcgen05.wait::ld.sync.aligned;" ::: "memory");
}
__device__ __forceinline__ uint32_t tmem_alloc_w8(uint32_t sptr) {
    asm volatile(
        "tcgen05.alloc.cta_group::1.sync.aligned.shared::cta.b32 [%0], %1;"
        :: "r"(sptr), "r"(128u) : "memory");
    uint32_t tm;
    asm volatile("ld.shared.b32 %0, [%1];" : "=r"(tm) : "r"(sptr));
    return tm;
}
__device__ __forceinline__ void tmem_free_w8(uint32_t tm) {
    asm volatile("tcgen05.relinquish_alloc_permit.cta_group::1.sync.aligned;");
    asm volatile("tcgen05.dealloc.cta_group::1.sync.aligned.b32 %0, %1;"
                 :: "r"(tm), "r"(128u));
}
#endif // TC_OK

// ============ K1/K5: Y = X @ W^T + bias  (tf32 3x split, prefetch) ==========
// 288 threads: t<256 loaders, warp 8 MMA. 2 buffers of 64KB: Ah|Al|Bh|Bl.
#define PF_BUF   65536
#define PF_MBAR  131072
#define PF_TPTR  131088
#define PF_BIAS  131104
#define PF_TOTAL 131648

__global__ __launch_bounds__(288, 1) void k_pf(
    const float* __restrict__ X0, const float* __restrict__ X1,
    const float* __restrict__ X2, const float* __restrict__ W,
    const float* __restrict__ bias,
    float* __restrict__ Y0, float* __restrict__ Y1, float* __restrict__ Y2)
{
    extern __shared__ char sm[];
    const int z = blockIdx.z;
    const float* X = (z == 0) ? X0 : (z == 1) ? X1 : X2;
    float* Y = (z == 0) ? Y0 : (z == 1) ? Y1 : Y2;
    const int t = threadIdx.x;
    const int bm = blockIdx.y * 128, bn = blockIdx.x * 128;

#if TC_OK
    const uint32_t sbase = smem_u32(sm);
    const uint32_t mb0 = sbase + PF_MBAR, mb1 = sbase + PF_MBAR + 8;
    uint32_t tmem = 0;

    if (t >= 256) {
        if (t == 256) { mbar_init(mb0, 1); mbar_init(mb1, 1); }
        tmem = tmem_alloc_w8(sbase + PF_TPTR);
    } else if (t < 128) {
        ((float*)(sm + PF_BIAS))[t] = bias[bn + t];
    }
    __syncthreads();
    if (t < 256)
        asm volatile("ld.shared.b32 %0, [%1];" : "=r"(tmem) : "r"(sbase + PF_TPTR));

    const int row = t >> 1;          // wait, per-i mapping below
    (void)row;
    int ph[2] = {0, 0};
    float4 ca[4], cb[4], pa[4], pb[4];

    // preload chunk 0
    if (t < 256) {
#pragma unroll
        for (int i = 0; i < 4; i++) {
            int idx = i * 256 + t, r = idx >> 3, c4 = idx & 7;
            ca[i] = *(const float4*)(X + (size_t)(bm + r) * 768 + c4 * 4);
            cb[i] = *(const float4*)(W + (size_t)(bn + r) * 768 + c4 * 4);
        }
    }

    for (int c = 0; c < 24; c++) {
        const int bf = c & 1;
        char* base = sm + bf * PF_BUF;
        if (t < 256) {
            if (c < 23) {            // prefetch chunk c+1 BEFORE any wait
                const int k0 = (c + 1) * 32;
#pragma unroll
                for (int i = 0; i < 4; i++) {
                    int idx = i * 256 + t, r = idx >> 3, c4 = idx & 7;
                    pa[i] = *(const float4*)(X + (size_t)(bm + r) * 768 + k0 + c4 * 4);
                    pb[i] = *(const float4*)(W + (size_t)(bn + r) * 768 + k0 + c4 * 4);
                }
            }
            if (c >= 2) { mbar_wait((bf ? mb1 : mb0), ph[bf]); ph[bf] ^= 1; }
#pragma unroll
            for (int i = 0; i < 4; i++) {
                int idx = i * 256 + t, r = idx >> 3, c4 = idx & 7;
                uint32_t off = SWZ((uint32_t)(r * 128 + c4 * 16));
                float4 h, l;
                split4(ca[i], h, l);
                *(float4*)(base + off)         = h;
                *(float4*)(base + 16384 + off) = l;
                split4(cb[i], h, l);
                *(float4*)(base + 32768 + off) = h;
                *(float4*)(base + 49152 + off) = l;
            }
            asm volatile("fence.proxy.async.shared::cta;" ::: "memory");
        }
        __syncthreads();
        if (t >= 256 && elect_one()) {
            issue12(tmem, sbase + bf * PF_BUF, 16384, 32768, 49152,
                    IDESC_N128, c == 0);
            tc_commit(bf ? mb1 : mb0);
        }
        if (t < 256) {
#pragma unroll
            for (int i = 0; i < 4; i++) { ca[i] = pa[i]; cb[i] = pb[i]; }
        }
    }

    if (t < 128) {
        mbar_wait(mb0, ph[0]);
        mbar_wait(mb1, ph[1]);
        asm volatile("tcgen05.fence::after_thread_sync;" ::: "memory");
        float* yrow = Y + (size_t)(bm + t) * 768 + bn;
        const float* sb = (const float*)(sm + PF_BIAS);
#pragma unroll
        for (int nb = 0; nb < 4; nb++) {
            uint32_t r[32];
            ldtm32(r, tmem + nb * 32);
            float f[32];
#pragma unroll
            for (int j = 0; j < 32; j++)
                f[j] = __uint_as_float(r[j]) + sb[nb * 32 + j];
#pragma unroll
            for (int j4 = 0; j4 < 8; j4++)
                *(float4*)(yrow + nb * 32 + j4 * 4) =
                    make_float4(f[j4 * 4], f[j4 * 4 + 1], f[j4 * 4 + 2], f[j4 * 4 + 3]);
        }
        asm volatile("tcgen05.fence::before_thread_sync;" ::: "memory");
    }
    __syncthreads();
    if (t >= 256) tmem_free_w8(tmem);
#else
    if (t < 128) {
        for (int n = 0; n < 128; n++) {
            float acc = bias[bn + n];
            const float* xr = X + (size_t)(bm + t) * 768;
            const float* wr = W + (size_t)(bn + n) * 768;
            for (int kk = 0; kk < 768; kk++) acc = fmaf(xr[kk], wr[kk], acc);
            Y[(size_t)(bm + t) * 768 + bn + n] = acc;
        }
    }
#endif
}

// ============ K2: L0 = 0.125 * Qh @ Kh^T  (tf32 3x split, K=64) =============
// Single 64KB buffer, 2 chunks of K=32, serialized via one mbar.
#define QK_MBAR  65536
#define QK_TPTR  65552
#define QK_TOTAL 65600

__global__ __launch_bounds__(288, 1) void k_qk_tc()
{
    extern __shared__ char sm[];
    const int bh = blockIdx.z;
    const int b = bh / HH, h = bh % HH;
    const float* Aq = g_qf + (size_t)b * SS * DD + h * HDD;
    const float* Bk = g_kf + (size_t)b * SS * DD + h * HDD;
    float* C = g_L0 + (size_t)bh * SS * SS;
    const int t = threadIdx.x;
    const int bm = blockIdx.y * 128, bn = blockIdx.x * 128;

#if TC_OK
    const uint32_t sbase = smem_u32(sm);
    const uint32_t mb = sbase + QK_MBAR;
    uint32_t tmem = 0;
    if (t >= 256) {
        if (t == 256) mbar_init(mb, 1);
        tmem = tmem_alloc_w8(sbase + QK_TPTR);
    }
    __syncthreads();
    if (t < 256)
        asm volatile("ld.shared.b32 %0, [%1];" : "=r"(tmem) : "r"(sbase + QK_TPTR));

    float4 ca[4], cb[4], pa[4], pb[4];
    if (t < 256) {
#pragma unroll
        for (int i = 0; i < 4; i++) {
            int idx = i * 256 + t, r = idx >> 3, c4 = idx & 7;
            ca[i] = *(const float4*)(Aq + (size_t)(bm + r) * DD + c4 * 4);
            cb[i] = *(const float4*)(Bk + (size_t)(bn + r) * DD + c4 * 4);
        }
    }
    for (int c = 0; c < 2; c++) {
        if (t < 256) {
            if (c == 0) {
#pragma unroll
                for (int i = 0; i < 4; i++) {
                    int idx = i * 256 + t, r = idx >> 3, c4 = idx & 7;
                    pa[i] = *(const float4*)(Aq + (size_t)(bm + r) * DD + 32 + c4 * 4);
                    pb[i] = *(const float4*)(Bk + (size_t)(bn + r) * DD + 32 + c4 * 4);
                }
            } else {
                mbar_wait(mb, 0);   // chunk-0 MMAs done before overwrite
            }
#pragma unroll
            for (int i = 0; i < 4; i++) {
                int idx = i * 256 + t, r = idx >> 3, c4 = idx & 7;
                uint32_t off = SWZ((uint32_t)(r * 128 + c4 * 16));
                float4 hh, ll;
                split4(ca[i], hh, ll);
                *(float4*)(sm + off)         = hh;
                *(float4*)(sm + 16384 + off) = ll;
                split4(cb[i], hh, ll);
                *(float4*)(sm + 32768 + off) = hh;
                *(float4*)(sm + 49152 + off) = ll;
            }
            asm volatile("fence.proxy.async.shared::cta;" ::: "memory");
        }
        __syncthreads();
        if (t >= 256 && elect_one()) {
            issue12(tmem, sbase, 16384, 32768, 49152, IDESC_N128, c == 0);
            tc_commit(mb);
        }
        if (t < 256) {
#pragma unroll
            for (int i = 0; i < 4; i++) { ca[i] = pa[i]; cb[i] = pb[i]; }
        }
    }

    if (t < 128) {
        mbar_wait(mb, 1);
        asm volatile("tcgen05.fence::after_thread_sync;" ::: "memory");
        float* crow = C + (size_t)(bm + t) * SS + bn;
#pragma unroll
        for (int nb = 0; nb < 4; nb++) {
            uint32_t r[32];
            ldtm32(r, tmem + nb * 32);
#pragma unroll
            for (int j4 = 0; j4 < 8; j4++)
                *(float4*)(crow + nb * 32 + j4 * 4) = make_float4(
                    __uint_as_float(r[j4 * 4])     * 0.125f,
                    __uint_as_float(r[j4 * 4 + 1]) * 0.125f,
                    __uint_as_float(r[j4 * 4 + 2]) * 0.125f,
                    __uint_as_float(r[j4 * 4 + 3]) * 0.125f);
        }
        asm volatile("tcgen05.fence::before_thread_sync;" ::: "memory");
    }
    __syncthreads();
    if (t >= 256) tmem_free_w8(tmem);
#else
    if (t < 128) {
        for (int n = 0; n < 128; n++) {
            float acc = 0.f;
            for (int kk = 0; kk < 64; kk++)
                acc = fmaf(Aq[(size_t)(bm + t) * DD + kk],
                           Bk[(size_t)(bn + n) * DD + kk], acc);
            C[(size_t)(bm + t) * SS + bn + n] = acc * 0.125f;
        }
    }
#endif
}

// ============ V transpose + tf32 split: g_vt[bh][64][1024] ==================
__global__ __launch_bounds__(256) void k_vt()
{
    __shared__ float tile[128][65];
    const int bh = blockIdx.y;
    const int b = bh / HH, g = bh % HH;
    const int k0 = blockIdx.x * 128;
    const int t = threadIdx.x;
    const float* V = g_vf + (size_t)b * SS * DD + g * HDD;

#pragma unroll
    for (int i = 0; i < 8; i++) {
        int idx = i * 256 + t, r = idx >> 4, c4 = idx & 15;
        float4 v = *(const float4*)(V + (size_t)(k0 + r) * DD + c4 * 4);
        tile[r][c4 * 4 + 0] = v.x; tile[r][c4 * 4 + 1] = v.y;
        tile[r][c4 * 4 + 2] = v.z; tile[r][c4 * 4 + 3] = v.w;
    }
    __syncthreads();
    float* oh = g_vth + (size_t)bh * HDD * SS;
    float* ol = g_vtl + (size_t)bh * HDD * SS;
#pragma unroll
    for (int i = 0; i < 32; i++) {
        int idx = i * 256 + t, d = idx >> 7, r = idx & 127;
        float v = tile[r][d];
        float h = thi(v);
        oh[(size_t)d * SS + k0 + r] = h;
        ol[(size_t)d * SS + k0 + r] = v - h;
    }
}

// ============ K4: ctx = A @ Vt^T  (tf32 3x split, K=1024 pipeline) ==========
// 2 buffers of 48KB: Ah(16K)|Al(16K)|Bh(8K)|Bl(8K)
#define AV_BUF   49152
#define AV_MBAR  98304
#define AV_TPTR  98320
#define AV_TOTAL 98368

__global__ __launch_bounds__(288, 1) void k_av_tc()
{
    extern __shared__ char sm[];
    const int bh = blockIdx.y;
    const int b = bh / HH, g = bh % HH;
    const float* A  = g_A   + (size_t)bh * SS * SS;
    const float* Vh = g_vth + (size_t)bh * HDD * SS;
    const float* Vl = g_vtl + (size_t)bh * HDD * SS;
    float* C = g_ctx + (size_t)b * SS * DD + g * HDD;
    const int t = threadIdx.x;
    const int bm = blockIdx.x * 128;

#if TC_OK
    const uint32_t sbase = smem_u32(sm);
    const uint32_t mb0 = sbase + AV_MBAR, mb1 = sbase + AV_MBAR + 8;
    uint32_t tmem = 0;
    if (t >= 256) {
        if (t == 256) { mbar_init(mb0, 1); mbar_init(mb1, 1); }
        tmem = tmem_alloc_w8(sbase + AV_TPTR);
    }
    __syncthreads();
    if (t < 256)
        asm volatile("ld.shared.b32 %0, [%1];" : "=r"(tmem) : "r"(sbase + AV_TPTR));

    int ph[2] = {0, 0};
    float4 ca[4], pa[4];
    float4 cbh[2], cbl[2], pbh[2], pbl[2];

    if (t < 256) {
#pragma unroll
        for (int i = 0; i < 4; i++) {
            int idx = i * 256 + t, r = idx >> 3, c4 = idx & 7;
            ca[i] = *(const float4*)(A + (size_t)(bm + r) * SS + c4 * 4);
        }
#pragma unroll
        for (int i = 0; i < 2; i++) {
            int idx = i * 256 + t, r = idx >> 3, c4 = idx & 7;
            cbh[i] = *(const float4*)(Vh + (size_t)r * SS + c4 * 4);
            cbl[i] = *(const float4*)(Vl + (size_t)r * SS + c4 * 4);
        }
    }

    for (int c = 0; c < 32; c++) {
        const int bf = c & 1;
        char* base = sm + bf * AV_BUF;
        if (t < 256) {
            if (c < 31) {
                const int k0 = (c + 1) * 32;
#pragma unroll
                for (int i = 0; i < 4; i++) {
                    int idx = i * 256 + t, r = idx >> 3, c4 = idx & 7;
                    pa[i] = *(const float4*)(A + (size_t)(bm + r) * SS + k0 + c4 * 4);
                }
#pragma unroll
                for (int i = 0; i < 2; i++) {
                    int idx = i * 256 + t, r = idx >> 3, c4 = idx & 7;
                    pbh[i] = *(const float4*)(Vh + (size_t)r * SS + k0 + c4 * 4);
                    pbl[i] = *(const float4*)(Vl + (size_t)r * SS + k0 + c4 * 4);
                }
            }
            if (c >= 2) { mbar_wait((bf ? mb1 : mb0), ph[bf]); ph[bf] ^= 1; }
#pragma unroll
            for (int i = 0; i < 4; i++) {
                int idx = i * 256 + t, r = idx >> 3, c4 = idx & 7;
                uint32_t off = SWZ((uint32_t)(r * 128 + c4 * 16));
                float4 hh, ll;
                split4(ca[i], hh, ll);
                *(float4*)(base + off)         = hh;
                *(float4*)(base + 16384 + off) = ll;
            }
#pragma unroll
            for (int i = 0; i < 2; i++) {
                int idx = i * 256 + t, r = idx >> 3, c4 = idx & 7;
                uint32_t off = SWZ((uint32_t)(r * 128 + c4 * 16));
                *(float4*)(base + 32768 + off) = cbh[i];
                *(float4*)(base + 40960 + off) = cbl[i];
            }
            asm volatile("fence.proxy.async.shared::cta;" ::: "memory");
        }
        __syncthreads();
        if (t >= 256 && elect_one()) {
            issue12(tmem, sbase + bf * AV_BUF, 16384, 32768, 40960,
                    IDESC_N64, c == 0);
            tc_commit(bf ? mb1 : mb0);
        }
        if (t < 256) {
#pragma unroll
            for (int i = 0; i < 4; i++) ca[i] = pa[i];
#pragma unroll
            for (int i = 0; i < 2; i++) { cbh[i] = pbh[i]; cbl[i] = pbl[i]; }
        }
    }

    if (t < 128) {
        mbar_wait(mb0, ph[0]);
        mbar_wait(mb1, ph[1]);
        asm volatile("tcgen05.fence::after_thread_sync;" ::: "memory");
        float* crow = C + (size_t)(bm + t) * DD;
#pragma unroll
        for (int nb = 0; nb < 2; nb++) {
            uint32_t r[32];
            ldtm32(r, tmem + nb * 32);
#pragma unroll
            for (int j4 = 0; j4 < 8; j4++)
                *(float4*)(crow + nb * 32 + j4 * 4) = make_float4(
                    __uint_as_float(r[j4 * 4]),     __uint_as_float(r[j4 * 4 + 1]),
                    __uint_as_float(r[j4 * 4 + 2]), __uint_as_float(r[j4 * 4 + 3]));
        }
        asm volatile("tcgen05.fence::before_thread_sync;" ::: "memory");
    }
    __syncthreads();
    if (t >= 256) tmem_free_w8(tmem);
#else
    if (t < 128) {
        for (int n = 0; n < 64; n++) {
            float acc = 0.f;
            for (int kk = 0; kk < 1024; kk++)
                acc = fmaf(A[(size_t)(bm + t) * SS + kk],
                           Vh[(size_t)n * SS + kk] + Vl[(size_t)n * SS + kk], acc);
            C[(size_t)(bm + t) * DD + n] = acc;
        }
    }
#endif
}

// ---------------- FFMA-only exp ---------------------------------------------
__device__ __forceinline__ float fexp(float x) {
    float t = fmaxf(x * 1.4426950408889634f, -126.0f);
    float fi = floorf(t);
    float f = t - fi;
    float p = 1.5403530e-4f;
    p = fmaf(p, f, 1.3333558e-3f);
    p = fmaf(p, f, 9.6181291e-3f);
    p = fmaf(p, f, 5.5504109e-2f);
    p = fmaf(p, f, 2.4022651e-1f);
    p = fmaf(p, f, 6.9314718e-1f);
    p = fmaf(p, f, 1.0f);
    int e = (int)fi;
    return p * __int_as_float((e + 127) << 23);
}

// ---------------- K3: fused Wl-mix -> softmax -> Wp-mix ----------------------
__global__ __launch_bounds__(256) void k_softmix(
    const float* __restrict__ Wl, const float* __restrict__ bl,
    const float* __restrict__ Wp, const float* __restrict__ bp)
{
    __shared__ float sWl[144], sWp[144], sbl[12], sbp[12];
    __shared__ float red[12][8];
    __shared__ float sstat[12];
    __shared__ float sinv[12];

    const int t = threadIdx.x;
    if (t < 144) { sWl[t] = Wl[t]; sWp[t] = Wp[t]; }
    if (t < 12)  { sbl[t] = bl[t]; sbp[t] = bp[t]; }
    __syncthreads();

    const int q = blockIdx.x, b = blockIdx.y;
    const size_t base = (size_t)(b * HH) * SS * SS + (size_t)q * SS;

    float L[12][4];
#pragma unroll
    for (int g = 0; g < 12; g++) {
        float bv = sbl[g];
        L[g][0] = bv; L[g][1] = bv; L[g][2] = bv; L[g][3] = bv;
    }
#pragma unroll
    for (int h = 0; h < 12; h++) {
        float4 r = ((const float4*)(g_L0 + base + (size_t)h * SS * SS))[t];
#pragma unroll
        for (int g = 0; g < 12; g++) {
            float w = sWl[g * 12 + h];
            L[g][0] = fmaf(w, r.x, L[g][0]);
            L[g][1] = fmaf(w, r.y, L[g][1]);
            L[g][2] = fmaf(w, r.z, L[g][2]);
            L[g][3] = fmaf(w, r.w, L[g][3]);
        }
    }

    float mx[12];
#pragma unroll
    for (int g = 0; g < 12; g++)
        mx[g] = fmaxf(fmaxf(L[g][0], L[g][1]), fmaxf(L[g][2], L[g][3]));
#pragma unroll
    for (int o = 16; o; o >>= 1)
#pragma unroll
        for (int g = 0; g < 12; g++)
            mx[g] = fmaxf(mx[g], __shfl_xor_sync(0xffffffffu, mx[g], o));
    if ((t & 31) == 0)
#pragma unroll
        for (int g = 0; g < 12; g++) red[g][t >> 5] = mx[g];
    __syncthreads();
    if (t < 12) {
        float m = red[t][0];
#pragma unroll
        for (int w = 1; w < 8; w++) m = fmaxf(m, red[t][w]);
        sstat[t] = m;
    }
    __syncthreads();

    float smr[12];
#pragma unroll
    for (int g = 0; g < 12; g++) {
        float m = sstat[g];
        float p0 = fexp(L[g][0] - m);
        float p1 = fexp(L[g][1] - m);
        float p2 = fexp(L[g][2] - m);
        float p3 = fexp(L[g][3] - m);
        L[g][0] = p0; L[g][1] = p1; L[g][2] = p2; L[g][3] = p3;
        smr[g] = (p0 + p1) + (p2 + p3);
    }
#pragma unroll
    for (int o = 16; o; o >>= 1)
#pragma unroll
        for (int g = 0; g < 12; g++)
            smr[g] += __shfl_xor_sync(0xffffffffu, smr[g], o);
    __syncthreads();
    if ((t & 31) == 0)
#pragma unroll
        for (int g = 0; g < 12; g++) red[g][t >> 5] = smr[g];
    __syncthreads();
    if (t < 12) {
        float s = red[t][0];
#pragma unroll
        for (int w = 1; w < 8; w++) s += red[t][w];
        sinv[t] = 1.0f / s;
    }
    __syncthreads();

#pragma unroll
    for (int h = 0; h < 12; h++) {
        float iv = sinv[h];
        L[h][0] *= iv; L[h][1] *= iv; L[h][2] *= iv; L[h][3] *= iv;
    }

#pragma unroll
    for (int g = 0; g < 12; g++) {
        float bv = sbp[g];
        float a0 = bv, a1 = bv, a2 = bv, a3 = bv;
#pragma unroll
        for (int h = 0; h < 12; h++) {
            float w = sWp[g * 12 + h];
            a0 = fmaf(w, L[h][0], a0);
            a1 = fmaf(w, L[h][1], a1);
            a2 = fmaf(w, L[h][2], a2);
            a3 = fmaf(w, L[h][3], a3);
        }
        ((float4*)(g_A + base + (size_t)g * SS * SS))[t] = make_float4(a0, a1, a2, a3);
    }
}

// ---------------- launch ------------------------------------------------------
extern "C" void kernel_launch(void* const* d_in, const int* in_sizes, int n_in,
                              void* d_out, int out_size)
{
    const float* q  = (const float*)d_in[0];
    const float* k  = (const float*)d_in[1];
    const float* v  = (const float*)d_in[2];
    const float* Wq = (const float*)d_in[3];
    const float* bq = (const float*)d_in[4];
    const float* Wl = (const float*)d_in[5];
    const float* bl = (const float*)d_in[6];
    const float* Wp = (const float*)d_in[7];
    const float* bp = (const float*)d_in[8];
    const float* Wf = (const float*)d_in[9];
    const float* bf = (const float*)d_in[10];
    float* out = (float*)d_out;

    cudaFuncSetAttribute(k_pf,    cudaFuncAttributeMaxDynamicSharedMemorySize, PF_TOTAL);
    cudaFuncSetAttribute(k_qk_tc, cudaFuncAttributeMaxDynamicSharedMemorySize, QK_TOTAL);
    cudaFuncSetAttribute(k_av_tc, cudaFuncAttributeMaxDynamicSharedMemorySize, AV_TOTAL);

    float* qf;  cudaGetSymbolAddress((void**)&qf,  g_qf);
    float* kf;  cudaGetSymbolAddress((void**)&kf,  g_kf);
    float* vf;  cudaGetSymbolAddress((void**)&vf,  g_vf);
    float* ctx; cudaGetSymbolAddress((void**)&ctx, g_ctx);

    k_pf     <<<dim3(6, 32, 3), 288, PF_TOTAL>>>(q, k, v, Wq, bq, qf, kf, vf);
    k_vt     <<<dim3(8, 48),    256>>>();
    k_qk_tc  <<<dim3(8, 8, 48), 288, QK_TOTAL>>>();
    k_softmix<<<dim3(1024, 4),  256>>>(Wl, bl, Wp, bp);
    k_av_tc  <<<dim3(8, 48),    288, AV_TOTAL>>>();
    k_pf     <<<dim3(6, 32, 1), 288, PF_TOTAL>>>(ctx, ctx, ctx, Wf, bf, out, out, out);
}